// round 14
// baseline (speedup 1.0000x reference)
#include <cuda_runtime.h>
#include <math.h>

#define IN_F   512
#define HID    256
#define BATCH  1024
#define CAP0   64           // layer-0 candidates (mean 32, +5.9 sigma)
#define CAP1   96           // layer-1 candidates (first count>=16 is <=64)

// Column-major (transposed) edge masks.
// Layer 0: column i (512 cols), 8 words of 32 output bits:   g_cmask0[i*8 + w]
// Layer 1: column j (256 cols), 16 words stored INTERLEAVED: word pair for
//          warp w = outputs {32w..} and {32(w+8)..} at g_cmask1[j*16 + 2w +0/1]
__device__ unsigned int g_cmask0[IN_F * (HID / 32)];
__device__ unsigned int g_cmask1[HID  * (IN_F / 32)];
__device__ unsigned int g_ctr0;     // layer-0 mask completion (512/launch)
__device__ unsigned int g_ctr1;     // layer-1 mask completion (512/launch)

// ---------------------------------------------------------------------------
// 32x32 bit-matrix transpose across a warp (5 shfl_xor steps, literal masks).
// ---------------------------------------------------------------------------
__device__ __forceinline__ unsigned warp_bit_transpose(unsigned x, int lane)
{
    unsigned y;
    y = __shfl_xor_sync(0xFFFFFFFFu, x, 16);
    x = (lane & 16) ? ((x & 0xFFFF0000u) | ((y >> 16) & 0x0000FFFFu))
                    : ((x & 0x0000FFFFu) | ((y & 0x0000FFFFu) << 16));
    y = __shfl_xor_sync(0xFFFFFFFFu, x, 8);
    x = (lane & 8)  ? ((x & 0xFF00FF00u) | ((y >> 8) & 0x00FF00FFu))
                    : ((x & 0x00FF00FFu) | ((y & 0x00FF00FFu) << 8));
    y = __shfl_xor_sync(0xFFFFFFFFu, x, 4);
    x = (lane & 4)  ? ((x & 0xF0F0F0F0u) | ((y >> 4) & 0x0F0F0F0Fu))
                    : ((x & 0x0F0F0F0Fu) | ((y & 0x0F0F0F0Fu) << 4));
    y = __shfl_xor_sync(0xFFFFFFFFu, x, 2);
    x = (lane & 2)  ? ((x & 0xCCCCCCCCu) | ((y >> 2) & 0x33333333u))
                    : ((x & 0x33333333u) | ((y & 0x33333333u) << 2));
    y = __shfl_xor_sync(0xFFFFFFFFu, x, 1);
    x = (lane & 1)  ? ((x & 0xAAAAAAAAu) | ((y >> 1) & 0x55555555u))
                    : ((x & 0x55555555u) | ((y & 0x55555555u) << 1));
    return x;
}

// One window step of the first-hit walk for one output (exact tie rescan).
__device__ __forceinline__ void walk_step(
    float& v, unsigned& q, bool& done, bool& pend,
    unsigned hits, const unsigned* __restrict__ keys,   // skey + base
    const float* __restrict__ vals, unsigned lastb, bool isMin)
{
    unsigned scanb = 0;
    if (!done) {
        if (hits) {
            int p = __ffs(hits) - 1;
            unsigned k0 = keys[p];
            q = k0 >> 9;
            v = vals[k0 & 511u];
            done = true; pend = true;
            scanb = hits & (0xFFFFFFFEu << p);          // bits strictly > p
        }
    } else if (pend) {
        scanb = hits;
    }
    while (scanb) {                                      // same-bucket rescan
        int p2 = __ffs(scanb) - 1;
        scanb &= scanb - 1;
        unsigned k2 = keys[p2];
        if ((k2 >> 9) != q) { pend = false; break; }
        float u = vals[k2 & 511u];
        v = isMin ? fminf(v, u) : fmaxf(v, u);
    }
    if (pend) pend = (lastb == q);                       // bucket spills on?
}

// Gumbel-argmax edge predicate (tie -> e=0; monotone shortcut when logits eq).
__device__ __forceinline__ bool edge_pred(float2 l, float2 u)
{
    const float LO = 1e-10f;
    const float HI = 1.0f - 1e-10f;
    float ca = fminf(fmaxf(u.x, LO), HI);
    float cb = fminf(fmaxf(u.y, LO), HI);
    if (l.x == l.y) return cb > ca;
    float g0 = -logf(-logf(ca));
    float g1 = -logf(-logf(cb));
    return (l.y + g1) > (l.x + g0);
}

// Acquire-spin until counter reaches target (thread 0 only).
__device__ __forceinline__ void spin_until(unsigned* ctr, unsigned target)
{
    unsigned v;
    do {
        asm volatile("ld.acquire.gpu.global.u32 %0, [%1];"
                     : "=r"(v) : "l"(ctr) : "memory");
    } while (v < target);
}

// ---------------------------------------------------------------------------
// SINGLE fused kernel, one block per batch row (1024 blocks, co-resident).
// Phase A: block builds its 8 mask words; split counters ctr0/ctr1.
// Layer 0: threshold prefix (x < 1/16) + warp-0 rank sort + bit-parallel walk.
// Layer 1: adaptive prefix with ROBUST count: halve tau from blockmax/2 until
//          __syncthreads_count(h >= tau) >= 16 (kills the Gumbel-tail case
//          that regressed round 13), then rank sort + walk. Overflow/no-hit
//          -> exact brute-force fallback.
// ---------------------------------------------------------------------------
__global__ __launch_bounds__(256, 8)
void fused_kernel(const float* __restrict__ x,
                  const float* __restrict__ logits0, const float* __restrict__ u0,
                  const float* __restrict__ logits1, const float* __restrict__ u1,
                  float* __restrict__ out)
{
    __shared__ unsigned char mtile[32][9];  // mask tile (32 o x 8 i), padded
    __shared__ unsigned buf0 [CAP0];  // unsorted layer-0 candidates
    __shared__ unsigned skey0[CAP0];  // sorted layer-0 prefix keys
    __shared__ unsigned buf1 [CAP1];  // unsorted layer-1 candidates
    __shared__ unsigned skey1[CAP1];  // sorted layer-1 prefix keys
    __shared__ float    sval [IN_F];  // exact x row
    __shared__ float    shv  [HID];   // exact h row
    __shared__ float    wmaxs[8];     // per-warp h maxima
    __shared__ unsigned n0s, n1s;

    const int b    = blockIdx.x;
    const int t    = threadIdx.x;     // 0..255
    const int lane = t & 31;
    const int w    = t >> 5;

    // ---- hoist x loads: overlap x DRAM latency with mask edge reads -------
    float v0 = x[b * IN_F + t];
    float v1 = x[b * IN_F + t + 256];
    sval[t] = v0; sval[t + 256] = v1;
    if (t == 0) { n0s = 0; n1s = 0; } // covered by phase A's barrier

    // =================== Phase A: build this block's 8 mask words ==========
    {
        const int olc = t >> 3;               // 0..31 local output row
        const int ilc = t & 7;                // 0..7  local input col
        if (b < 512) {                        // layer 0 tile: 8 x 64 grid
            int tile_o = b >> 6;              // 0..7
            int tile_i = b & 63;              // 0..63
            int o = tile_o * 32 + olc;
            int i = tile_i * 8 + ilc;
            int e = o * IN_F + i;             // float2 index (E=2)
            bool pred = edge_pred(reinterpret_cast<const float2*>(logits0)[e],
                                  reinterpret_cast<const float2*>(u0)[e]);
            mtile[olc][ilc] = pred ? 1 : 0;
            __syncthreads();
            unsigned bal = __ballot_sync(0xFFFFFFFFu, mtile[lane][w] != 0);
            if (lane == 0) {
                int icol = tile_i * 8 + w;
                g_cmask0[icol * 8 + tile_o] = bal;
            }
        } else {                              // layer 1 tile: 16 x 32 grid
            int bb = b - 512;
            int tile_o = bb >> 5;             // 0..15
            int tile_j = bb & 31;             // 0..31
            int o = tile_o * 32 + olc;
            int j = tile_j * 8 + ilc;
            int e = o * HID + j;
            bool pred = edge_pred(reinterpret_cast<const float2*>(logits1)[e],
                                  reinterpret_cast<const float2*>(u1)[e]);
            mtile[olc][ilc] = pred ? 1 : 0;
            __syncthreads();
            unsigned bal = __ballot_sync(0xFFFFFFFFu, mtile[lane][w] != 0);
            if (lane == 0) {
                int jcol = tile_j * 8 + w;
                int slot = 2 * (tile_o & 7) + (tile_o >> 3);  // interleaved
                g_cmask1[jcol * 16 + slot] = bal;
            }
        }
    }
    unsigned tgt = 0;                 // epoch target, valid in thread 0 only
    __threadfence();                  // release mask stores
    if (t == 0) {
        unsigned old = atomicAdd((b < 512) ? &g_ctr0 : &g_ctr1, 1u);
        tgt = ((old >> 9) + 1u) << 9; // both counters hit this within launch
    }

    // ======== layer 0: threshold append (x < 1/16), keys ascending =========
    const float TAU0 = 0.0625f;       // exponent cut: tie groups never straddle
    if (v0 < TAU0) {
        unsigned p = atomicAdd(&n0s, 1u);
        if (p < CAP0) buf0[p] = (((__float_as_uint(v0) >> 9) << 9) | (unsigned)t);
    }
    if (v1 < TAU0) {
        unsigned p = atomicAdd(&n0s, 1u);
        if (p < CAP0) buf0[p] = (((__float_as_uint(v1) >> 9) << 9) | (unsigned)(t + 256));
    }
    __syncthreads();

    const unsigned n0raw = n0s;
    const bool     ovf0  = (n0raw > CAP0);
    const unsigned n0    = min(n0raw, (unsigned)CAP0);

    if (w == 0) {                     // warp 0 rank-sorts (exact, unique keys)
        unsigned e0 = (lane      < (int)n0) ? buf0[lane]      : 0xFFFFFFFFu;
        unsigned e1 = (lane + 32 < (int)n0) ? buf0[lane + 32] : 0xFFFFFFFFu;
        int r0 = 0, r1 = 0;
        for (int j = 0; j < (int)n0; j++) {
            unsigned kj = buf0[j];
            r0 += (kj < e0); r1 += (kj < e1);
        }
        if (lane      < (int)n0) skey0[r0] = e0;
        if (lane + 32 < (int)n0) skey0[r1] = e1;
    }
    if (t == 0) spin_until(&g_ctr0, tgt);
    __syncthreads();                  // publishes skey0 + layer-0 masks

    // ======== layer-0 walk over sorted prefix: warp w owns outputs 32w.. ===
    float h = 1.0f;                   // default: no selected edge
    {
        bool done = false, pend = false;
        unsigned qb = 0;
        for (unsigned base = 0; base < n0; base += 32) {
            unsigned keyl  = skey0[base + lane];         // &511 stays in bounds
            unsigned lastb = __shfl_sync(0xFFFFFFFFu, keyl, 31) >> 9;
            unsigned col   = g_cmask0[(keyl & 511u) * 8 + w];
            unsigned hits  = warp_bit_transpose(col, lane);
            unsigned rem   = n0 - base;
            if (rem < 32) hits &= (1u << rem) - 1u;      // mask junk positions
            walk_step(h, qb, done, pend, hits, skey0 + base, sval, lastb, true);
            if (__all_sync(0xFFFFFFFFu, done && !pend)) break;
        }
        if (ovf0 || !done) {                             // exact fallback
            if (ovf0) done = false;
            if (!done) {
                h = 1.0f;
                for (int i = 0; i < IN_F; i++)
                    if ((g_cmask0[i * 8 + w] >> lane) & 1u) h = fminf(h, sval[i]);
            }
        }
    }

    // ==== layer 1: adaptive prefix, ROBUST count (>=16 candidates) =========
    shv[t] = h;
    float wm = h;                     // block max of h (shfl + smem reduce)
#pragma unroll
    for (int d = 16; d >= 1; d >>= 1)
        wm = fmaxf(wm, __shfl_xor_sync(0xFFFFFFFFu, wm, d));
    if (lane == 0) wmaxs[w] = wm;
    __syncthreads();                  // publishes shv + wmaxs

    float mmax = wmaxs[0];
#pragma unroll
    for (int i = 1; i < 8; i++) mmax = fmaxf(mmax, wmaxs[i]);

    // halve tau until the block has at least 16 candidates (exact count via
    // __syncthreads_count -- each thread owns exactly one h). Expected ~1.5
    // iterations; first accepted count <= ~4x16 = 64 <= CAP1.
    float tau1 = 0.5f * mmax;
    for (int it = 0; it < 24; it++) {
        int cnt = __syncthreads_count(h >= tau1);
        if (cnt >= 16 || cnt == 256) break;
        tau1 *= 0.5f;
    }

    // key descending in h, unique: bucket = 0x4000 - (hbits>>16) (h in [0,1])
    unsigned hb   = __float_as_uint(h);
    unsigned key1 = ((0x4000u - (hb >> 16)) << 9) | (unsigned)t;
    if (h >= tau1) {
        unsigned p = atomicAdd(&n1s, 1u);
        if (p < CAP1) buf1[p] = key1;
    }
    __syncthreads();

    const unsigned n1raw = n1s;
    const bool     ovf1  = (n1raw > CAP1);
    const unsigned n1    = min(n1raw, (unsigned)CAP1);

    if (w == 0) {                     // warp 0 rank-sorts (ascending key =
        unsigned e0 = (lane      < (int)n1) ? buf1[lane]      : 0xFFFFFFFFu;
        unsigned e1 = (lane + 32 < (int)n1) ? buf1[lane + 32] : 0xFFFFFFFFu;
        unsigned e2 = (lane + 64 < (int)n1) ? buf1[lane + 64] : 0xFFFFFFFFu;
        int r0 = 0, r1 = 0, r2 = 0;   //  descending h)
        for (int j = 0; j < (int)n1; j++) {
            unsigned kj = buf1[j];
            r0 += (kj < e0); r1 += (kj < e1); r2 += (kj < e2);
        }
        if (lane      < (int)n1) skey1[r0] = e0;
        if (lane + 32 < (int)n1) skey1[r1] = e1;
        if (lane + 64 < (int)n1) skey1[r2] = e2;
    }
    if (t == 0) spin_until(&g_ctr1, tgt);
    __syncthreads();                  // publishes skey1 + layer-1 masks

    // ====== layer-1 walk: warp w owns words for o=t (a) and o=t+256 (b) ====
    float ra = 0.0f, rb = 0.0f;       // default: no selected edge
    {
        bool da = false, pa = false, db = false, pb = false;
        unsigned qa = 0, qv = 0;
        const uint2* __restrict__ cm1 = reinterpret_cast<const uint2*>(g_cmask1);
        for (unsigned base = 0; base < n1; base += 32) {
            unsigned keyl  = (base + lane < n1) ? skey1[base + lane] : 0u;
            unsigned lastb = __shfl_sync(0xFFFFFFFFu, keyl, 31) >> 9;
            uint2 cw = cm1[(keyl & 255u) * 8 + w];       // one LDG.64
            unsigned hta = warp_bit_transpose(cw.x, lane);
            unsigned htb = warp_bit_transpose(cw.y, lane);
            unsigned rem = n1 - base;
            if (rem < 32) { unsigned m = (1u << rem) - 1u; hta &= m; htb &= m; }
            walk_step(ra, qa, da, pa, hta, skey1 + base, shv, lastb, false);
            walk_step(rb, qv, db, pb, htb, skey1 + base, shv, lastb, false);
            if (__all_sync(0xFFFFFFFFu, da && !pa && db && !pb)) break;
        }
        if (ovf1) { da = false; db = false; }
        if (!da) {                                       // exact fallback a
            ra = 0.0f;
            for (int j = 0; j < HID; j++)
                if ((cm1[j * 8 + w].x >> lane) & 1u) ra = fmaxf(ra, shv[j]);
        }
        if (!db) {                                       // exact fallback b
            rb = 0.0f;
            for (int j = 0; j < HID; j++)
                if ((cm1[j * 8 + w].y >> lane) & 1u) rb = fmaxf(rb, shv[j]);
        }
    }

    out[b * IN_F + t]       = ra;
    out[b * IN_F + t + 256] = rb;
}

// ---------------------------------------------------------------------------
// kernel_launch: graph-capturable, allocation-free, ONE launch.
// Inputs: x, logits0, u0, logits1, u1. Output: float32 [1024,512].
// ---------------------------------------------------------------------------
extern "C" void kernel_launch(void* const* d_in, const int* in_sizes, int n_in,
                              void* d_out, int out_size)
{
    const float* x       = (const float*)d_in[0];
    const float* logits0 = (const float*)d_in[1];
    const float* u0      = (const float*)d_in[2];
    const float* logits1 = (const float*)d_in[3];
    const float* u1      = (const float*)d_in[4];
    float* out = (float*)d_out;

    fused_kernel<<<BATCH, 256>>>(x, logits0, u0, logits1, u1, out);
}

// round 15
// speedup vs baseline: 1.9612x; 1.9612x over previous
#include <cuda_runtime.h>
#include <math.h>

#define IN_F   512
#define HID    256
#define BATCH  1024
#define CAP0   64           // layer-0 candidate buffer (mean 32, +5.9 sigma)

// Column-major (transposed) edge masks.
// Layer 0: column i (512 cols), 8 words of 32 output bits:   g_cmask0[i*8 + w]
// Layer 1: column j (256 cols), 16 words stored INTERLEAVED: word pair for
//          warp w = outputs {32w..} and {32(w+8)..} at g_cmask1[j*16 + 2w +0/1]
__device__ unsigned int g_cmask0[IN_F * (HID / 32)];
__device__ unsigned int g_cmask1[HID  * (IN_F / 32)];
__device__ unsigned int g_ctr0;     // layer-0 mask completion (512/launch)
__device__ unsigned int g_ctr1;     // layer-1 mask completion (512/launch)

// ---------------------------------------------------------------------------
// 32x32 bit-matrix transpose across a warp (5 shfl_xor steps, literal masks).
// ---------------------------------------------------------------------------
__device__ __forceinline__ unsigned warp_bit_transpose(unsigned x, int lane)
{
    unsigned y;
    y = __shfl_xor_sync(0xFFFFFFFFu, x, 16);
    x = (lane & 16) ? ((x & 0xFFFF0000u) | ((y >> 16) & 0x0000FFFFu))
                    : ((x & 0x0000FFFFu) | ((y & 0x0000FFFFu) << 16));
    y = __shfl_xor_sync(0xFFFFFFFFu, x, 8);
    x = (lane & 8)  ? ((x & 0xFF00FF00u) | ((y >> 8) & 0x00FF00FFu))
                    : ((x & 0x00FF00FFu) | ((y & 0x00FF00FFu) << 8));
    y = __shfl_xor_sync(0xFFFFFFFFu, x, 4);
    x = (lane & 4)  ? ((x & 0xF0F0F0F0u) | ((y >> 4) & 0x0F0F0F0Fu))
                    : ((x & 0x0F0F0F0Fu) | ((y & 0x0F0F0F0Fu) << 4));
    y = __shfl_xor_sync(0xFFFFFFFFu, x, 2);
    x = (lane & 2)  ? ((x & 0xCCCCCCCCu) | ((y >> 2) & 0x33333333u))
                    : ((x & 0x33333333u) | ((y & 0x33333333u) << 2));
    y = __shfl_xor_sync(0xFFFFFFFFu, x, 1);
    x = (lane & 1)  ? ((x & 0xAAAAAAAAu) | ((y >> 1) & 0x55555555u))
                    : ((x & 0x55555555u) | ((y & 0x55555555u) << 1));
    return x;
}

// One window step of the first-hit walk for one output (exact tie rescan).
__device__ __forceinline__ void walk_step(
    float& v, unsigned& q, bool& done, bool& pend,
    unsigned hits, const unsigned* __restrict__ keys,   // skey + base
    const float* __restrict__ vals, unsigned lastb, bool isMin)
{
    unsigned scanb = 0;
    if (!done) {
        if (hits) {
            int p = __ffs(hits) - 1;
            unsigned k0 = keys[p];
            q = k0 >> 9;
            v = vals[k0 & 511u];
            done = true; pend = true;
            scanb = hits & (0xFFFFFFFEu << p);          // bits strictly > p
        }
    } else if (pend) {
        scanb = hits;
    }
    while (scanb) {                                      // same-bucket rescan
        int p2 = __ffs(scanb) - 1;
        scanb &= scanb - 1;
        unsigned k2 = keys[p2];
        if ((k2 >> 9) != q) { pend = false; break; }
        float u = vals[k2 & 511u];
        v = isMin ? fminf(v, u) : fmaxf(v, u);
    }
    if (pend) pend = (lastb == q);                       // bucket spills on?
}

// Gumbel-argmax edge predicate (tie -> e=0; monotone shortcut when logits eq).
__device__ __forceinline__ bool edge_pred(float2 l, float2 u)
{
    const float LO = 1e-10f;
    const float HI = 1.0f - 1e-10f;
    float ca = fminf(fmaxf(u.x, LO), HI);
    float cb = fminf(fmaxf(u.y, LO), HI);
    if (l.x == l.y) return cb > ca;
    float g0 = -logf(-logf(ca));
    float g1 = -logf(-logf(cb));
    return (l.y + g1) > (l.x + g0);
}

// Acquire-spin until counter reaches target.
__device__ __forceinline__ void spin_until(unsigned* ctr, unsigned target)
{
    unsigned v;
    do {
        asm volatile("ld.acquire.gpu.global.u32 %0, [%1];"
                     : "=r"(v) : "l"(ctr) : "memory");
    } while (v < target);
}

// ---------------------------------------------------------------------------
// SINGLE fused kernel, one block per batch row (1024 blocks, co-resident).
// Phase A: block builds its 8 mask words; split counters ctr0/ctr1.
// Layer 0: threshold prefix (x < 1/16) + warp-0 rank sort (sentinel-padded,
//          fixed uint4 loop) + bit-parallel walk. ctr0 spin runs on thread
//          255 (warp 7) CONCURRENTLY with warp 0's sort.
// Layer 1: log-bucket counting sort of h + walk (round-12 logic, verified).
// ---------------------------------------------------------------------------
__global__ __launch_bounds__(256, 8)
void fused_kernel(const float* __restrict__ x,
                  const float* __restrict__ logits0, const float* __restrict__ u0,
                  const float* __restrict__ logits1, const float* __restrict__ u1,
                  float* __restrict__ out)
{
    __shared__ unsigned char mtile[32][9];  // mask tile (32 o x 8 i), padded
    __shared__ alignas(16) unsigned buf0[CAP0];  // unsorted layer-0 candidates
    __shared__ unsigned skey0[CAP0];  // sorted layer-0 prefix keys
    __shared__ float    sval [IN_F];  // exact x row
    __shared__ float    shv  [HID];   // exact h row
    __shared__ unsigned cnt  [HID];   // layer-1 counts / offsets
    __shared__ unsigned skey1[HID];   // layer-1 sorted keys
    __shared__ unsigned wsum[8];
    __shared__ unsigned n0s, tgts;

    const int b    = blockIdx.x;
    const int t    = threadIdx.x;     // 0..255
    const int lane = t & 31;
    const int w    = t >> 5;

    // ---- hoist x loads: overlap x DRAM latency with mask edge reads -------
    float v0 = x[b * IN_F + t];
    float v1 = x[b * IN_F + t + 256];
    sval[t] = v0; sval[t + 256] = v1;
    if (t == 0) n0s = 0;              // covered by phase A's barrier
    if (t < CAP0) buf0[t] = 0xFFFFFFFFu;  // sentinel > any real key

    // =================== Phase A: build this block's 8 mask words ==========
    {
        const int olc = t >> 3;               // 0..31 local output row
        const int ilc = t & 7;                // 0..7  local input col
        if (b < 512) {                        // layer 0 tile: 8 x 64 grid
            int tile_o = b >> 6;              // 0..7
            int tile_i = b & 63;              // 0..63
            int o = tile_o * 32 + olc;
            int i = tile_i * 8 + ilc;
            int e = o * IN_F + i;             // float2 index (E=2)
            bool pred = edge_pred(reinterpret_cast<const float2*>(logits0)[e],
                                  reinterpret_cast<const float2*>(u0)[e]);
            mtile[olc][ilc] = pred ? 1 : 0;
            __syncthreads();
            unsigned bal = __ballot_sync(0xFFFFFFFFu, mtile[lane][w] != 0);
            if (lane == 0) {
                int icol = tile_i * 8 + w;
                g_cmask0[icol * 8 + tile_o] = bal;
            }
        } else {                              // layer 1 tile: 16 x 32 grid
            int bb = b - 512;
            int tile_o = bb >> 5;             // 0..15
            int tile_j = bb & 31;             // 0..31
            int o = tile_o * 32 + olc;
            int j = tile_j * 8 + ilc;
            int e = o * HID + j;
            bool pred = edge_pred(reinterpret_cast<const float2*>(logits1)[e],
                                  reinterpret_cast<const float2*>(u1)[e]);
            mtile[olc][ilc] = pred ? 1 : 0;
            __syncthreads();
            unsigned bal = __ballot_sync(0xFFFFFFFFu, mtile[lane][w] != 0);
            if (lane == 0) {
                int jcol = tile_j * 8 + w;
                int slot = 2 * (tile_o & 7) + (tile_o >> 3);  // interleaved
                g_cmask1[jcol * 16 + slot] = bal;
            }
        }
    }
    unsigned tgt = 0;                 // epoch target, valid in thread 0 only
    __threadfence();                  // release mask stores
    if (t == 0) {
        unsigned old = atomicAdd((b < 512) ? &g_ctr0 : &g_ctr1, 1u);
        tgt = ((old >> 9) + 1u) << 9; // both counters hit this within launch
        tgts = tgt;                   // hand to spin thread (barrier below)
    }

    // ======== layer 0: threshold append (x < 1/16), keys ascending =========
    const float TAU0 = 0.0625f;       // exponent cut: tie groups never straddle
    if (v0 < TAU0) {
        unsigned p = atomicAdd(&n0s, 1u);
        if (p < CAP0) buf0[p] = (((__float_as_uint(v0) >> 9) << 9) | (unsigned)t);
    }
    if (v1 < TAU0) {
        unsigned p = atomicAdd(&n0s, 1u);
        if (p < CAP0) buf0[p] = (((__float_as_uint(v1) >> 9) << 9) | (unsigned)(t + 256));
    }
    __syncthreads();                  // publishes buf0, n0s, tgts

    const unsigned n0raw = n0s;
    const bool     ovf0  = (n0raw > CAP0);
    const unsigned n0    = min(n0raw, (unsigned)CAP0);

    // warp 0 rank-sorts (sentinel-padded fixed loop) WHILE thread 255 spins
    if (w == 0) {
        unsigned e0 = buf0[lane];
        unsigned e1 = buf0[lane + 32];
        int r0 = 0, r1 = 0;
        const uint4* b4 = reinterpret_cast<const uint4*>(buf0);
#pragma unroll
        for (int j4 = 0; j4 < CAP0 / 4; j4++) {          // 16 LDS.128
            uint4 k4 = b4[j4];
            r0 += (int)(k4.x < e0) + (int)(k4.y < e0)
                + (int)(k4.z < e0) + (int)(k4.w < e0);
            r1 += (int)(k4.x < e1) + (int)(k4.y < e1)
                + (int)(k4.z < e1) + (int)(k4.w < e1);
        }
        if (lane      < (int)n0) skey0[r0] = e0;         // sentinels excluded
        if (lane + 32 < (int)n0) skey0[r1] = e1;
    }
    if (t == 255) spin_until(&g_ctr0, tgts);             // overlaps the sort
    __syncthreads();                  // publishes skey0 + layer-0 masks

    // ======== layer-0 walk over sorted prefix: warp w owns outputs 32w.. ===
    float h = 1.0f;                   // default: no selected edge
    {
        bool done = false, pend = false;
        unsigned qb = 0;
        for (unsigned base = 0; base < n0; base += 32) {
            unsigned keyl  = skey0[base + lane];         // &511 stays in bounds
            unsigned lastb = __shfl_sync(0xFFFFFFFFu, keyl, 31) >> 9;
            unsigned col   = g_cmask0[(keyl & 511u) * 8 + w];
            unsigned hits  = warp_bit_transpose(col, lane);
            unsigned rem   = n0 - base;
            if (rem < 32) hits &= (1u << rem) - 1u;      // mask junk positions
            walk_step(h, qb, done, pend, hits, skey0 + base, sval, lastb, true);
            if (__all_sync(0xFFFFFFFFu, done && !pend)) break;
        }
        if (ovf0 || !done) {                             // exact fallback
            if (ovf0) done = false;
            if (!done) {
                h = 1.0f;
                for (int i = 0; i < IN_F; i++)
                    if ((g_cmask0[i * 8 + w] >> lane) & 1u) h = fminf(h, sval[i]);
            }
        }
    }
    __syncthreads();                  // walks done before smem reuse

    // ====== layer-1 sort: counting sort of h, LOG buckets, descending ======
    shv[t] = h;
    cnt[t] = 0;
    __syncthreads();

    // bucket = clamp((hbits>>19)-1792, 0, 255): exp + top-4 mantissa bits,
    // monotone in h >= 0; h <= 1.0 -> bucket <= 240.
    unsigned hb  = __float_as_uint(h);
    int bkt = min(max((int)(hb >> 19) - 1792, 0), 255);
    int bd  = 255 - bkt;              // descending
    unsigned rr = atomicAdd(&cnt[bd], 1u);
    __syncthreads();

    unsigned c = cnt[t], scn = c;
#pragma unroll
    for (int d = 1; d < 32; d <<= 1) {
        unsigned o = __shfl_up_sync(0xFFFFFFFFu, scn, d);
        if (lane >= d) scn += o;
    }
    if (lane == 31) wsum[w] = scn;
    __syncthreads();
    {
        unsigned ws = (lane < 8) ? wsum[lane] : 0u;
#pragma unroll
        for (int d = 1; d < 8; d <<= 1) {
            unsigned o = __shfl_up_sync(0xFFFFFFFFu, ws, d);
            if (lane >= d) ws += o;
        }
        unsigned wx = __shfl_sync(0xFFFFFFFFu, ws, (w == 0) ? 0 : (w - 1));
        if (w == 0) wx = 0;
        cnt[t] = wx + scn - c;
    }
    __syncthreads();

    skey1[cnt[bd] + rr] = ((unsigned)bd << 9) | (unsigned)t;

    // ---- wait for layer-1 mask words (overlapped walk0 + sort already) ----
    if (t == 0) spin_until(&g_ctr1, tgt);
    __syncthreads();                  // publishes skey1 AND mask visibility

    // ====== layer-1 walk: warp w owns words for o=t (a) and o=t+256 (b) ====
    float ra = 0.0f, rb = 0.0f;       // default: no selected edge
    {
        bool da = false, pa = false, db = false, pb = false;
        unsigned qa = 0, qv = 0;
        const uint2* __restrict__ cm1 = reinterpret_cast<const uint2*>(g_cmask1);
        for (int base = 0; base < HID; base += 32) {
            unsigned keyl  = skey1[base + lane];
            unsigned lastb = __shfl_sync(0xFFFFFFFFu, keyl, 31) >> 9;
            uint2 cw = cm1[(keyl & 511u) * 8 + w];       // one LDG.64
            unsigned hta = warp_bit_transpose(cw.x, lane);
            unsigned htb = warp_bit_transpose(cw.y, lane);
            walk_step(ra, qa, da, pa, hta, skey1 + base, shv, lastb, false);
            walk_step(rb, qv, db, pb, htb, skey1 + base, shv, lastb, false);
            if (__all_sync(0xFFFFFFFFu, da && !pa && db && !pb)) break;
        }
    }

    out[b * IN_F + t]       = ra;
    out[b * IN_F + t + 256] = rb;
}

// ---------------------------------------------------------------------------
// kernel_launch: graph-capturable, allocation-free, ONE launch.
// Inputs: x, logits0, u0, logits1, u1. Output: float32 [1024,512].
// ---------------------------------------------------------------------------
extern "C" void kernel_launch(void* const* d_in, const int* in_sizes, int n_in,
                              void* d_out, int out_size)
{
    const float* x       = (const float*)d_in[0];
    const float* logits0 = (const float*)d_in[1];
    const float* u0      = (const float*)d_in[2];
    const float* logits1 = (const float*)d_in[3];
    const float* u1      = (const float*)d_in[4];
    float* out = (float*)d_out;

    fused_kernel<<<BATCH, 256>>>(x, logits0, u0, logits1, u1, out);
}